// round 3
// baseline (speedup 1.0000x reference)
#include <cuda_runtime.h>

#define NTHREADS 512
#define TLEN 4096
#define MROW 4112                     // modes row stride (floats), 16B aligned, padded

#define SW(e) ((e) ^ ((((unsigned)(e))>>3)&15u))   // bank swizzle for FFT buffers

struct __align__(16) Smem {
    float2 buf0[TLEN];     // FFT ping (swizzled)
    float2 buf1[TLEN];     // FFT pong (swizzled)
    float2 xsave[TLEN];    // Y2 = X*S2 (swizzled), source of IFFT #2
    float2 tw[1024];       // exp(-2*pi*i*j/4096), j<1024
    float  modes[3][MROW]; // 3 merged filtered modes (real, linear)
    int    hist[16][36];
    float  red[16][20];
    float  totals[20];
    int    cnt[36];
    float  xnyq;
};

__device__ __forceinline__ float2 cadd(float2 a, float2 b){ return make_float2(a.x+b.x, a.y+b.y); }
__device__ __forceinline__ float2 csub(float2 a, float2 b){ return make_float2(a.x-b.x, a.y-b.y); }
__device__ __forceinline__ float2 cmul(float2 a, float2 b){
    return make_float2(fmaf(a.x,b.x,-a.y*b.y), fmaf(a.x,b.y, a.y*b.x));
}

// Stockham autosort radix-8 FFT, 4096 pts, 4 stages. First stage reads src0,
// ping-pongs bufB/bufA, result lands in bufA (natural order, swizzled layout).
template<bool INV>
__device__ void fft4096_r8(const float2* __restrict__ src0,
                           float2* __restrict__ bufA, float2* __restrict__ bufB,
                           const float2* __restrict__ tw, int tid)
{
    const float2* src = src0;
    float2* dst = bufB;
    #pragma unroll
    for (int stage = 0; stage < 4; ++stage) {
        const int slog = 3*stage;            // s = 8^stage
        const int p = tid >> slog;
        const int q = tid & ((1<<slog)-1);
        float2 x0 = src[SW(tid)];
        float2 x1 = src[SW(tid +  512)];
        float2 x2 = src[SW(tid + 1024)];
        float2 x3 = src[SW(tid + 1536)];
        float2 x4 = src[SW(tid + 2048)];
        float2 x5 = src[SW(tid + 2560)];
        float2 x6 = src[SW(tid + 3072)];
        float2 x7 = src[SW(tid + 3584)];
        const int ti = p << slog;            // p*s <= 511
        float2 w1 = tw[ti];
        float2 w2 = tw[2*ti];
        if (INV) { w1.y = -w1.y; w2.y = -w2.y; }
        float2 w3 = cmul(w1,w2);
        float2 w4 = cmul(w2,w2);
        float2 w5 = cmul(w2,w3);
        float2 w6 = cmul(w3,w3);
        float2 w7 = cmul(w3,w4);
        // radix-8 butterfly (DIF), X8[r] = sum_n x_n * w8^(rn)
        float2 t0=cadd(x0,x4), t1=cadd(x1,x5), t2=cadd(x2,x6), t3=cadd(x3,x7);
        float2 u0=csub(x0,x4), u1=csub(x1,x5), u2=csub(x2,x6), u3=csub(x3,x7);
        const float C8 = 0.70710678118654752f;
        const float2 om  = INV ? make_float2( C8,  C8) : make_float2( C8, -C8);
        const float2 om3 = INV ? make_float2(-C8,  C8) : make_float2(-C8, -C8);
        float2 v1 = cmul(u1, om);
        float2 v2 = INV ? make_float2(-u2.y, u2.x) : make_float2(u2.y, -u2.x); // (+-i)*u2
        float2 v3 = cmul(u3, om3);
        // even outputs: radix-4 on t
        float2 s02=cadd(t0,t2), d02=csub(t0,t2), s13=cadd(t1,t3), d13=csub(t1,t3);
        float2 jd = make_float2(-d13.y, d13.x);
        float2 X0 = cadd(s02, s13);
        float2 X4 = csub(s02, s13);
        float2 X2 = INV ? cadd(d02, jd) : csub(d02, jd);
        float2 X6 = INV ? csub(d02, jd) : cadd(d02, jd);
        // odd outputs: radix-4 on (u0, v1, v2, v3)
        float2 so=cadd(u0,v2), doo=csub(u0,v2), s13o=cadd(v1,v3), d13o=csub(v1,v3);
        float2 jdo = make_float2(-d13o.y, d13o.x);
        float2 X1 = cadd(so, s13o);
        float2 X5 = csub(so, s13o);
        float2 X3 = INV ? cadd(doo, jdo) : csub(doo, jdo);
        float2 X7 = INV ? csub(doo, jdo) : cadd(doo, jdo);
        const int st = 1 << slog;
        const int ob = q + (ti << 3);        // q + 8*s*p
        dst[SW(ob       )] = X0;
        dst[SW(ob +   st)] = cmul(w1, X1);
        dst[SW(ob + 2*st)] = cmul(w2, X2);
        dst[SW(ob + 3*st)] = cmul(w3, X3);
        dst[SW(ob + 4*st)] = cmul(w4, X4);
        dst[SW(ob + 5*st)] = cmul(w5, X5);
        dst[SW(ob + 6*st)] = cmul(w6, X6);
        dst[SW(ob + 7*st)] = cmul(w7, X7);
        __syncthreads();
        src = dst;
        dst = (dst == bufB) ? bufA : bufB;
    }
}

// Lehmer code of stable argsort of (a,b,c), matching reference id formula.
__device__ __forceinline__ int permid(float a, float b, float c)
{
    int i0 = (a <= b) ? 1 : 0;
    int i1 = (a <= c) ? 1 : 0;
    int i2 = (b <= c) ? 1 : 0;
    int idx = (i0 << 2) | (i1 << 1) | i2;
    const unsigned LUT = (5u<<0)|(3u<<4)|(0u<<8)|(2u<<12)|(4u<<16)|(0u<<20)|(1u<<24)|(0u<<28);
    return (int)((LUT >> (idx*4)) & 0xFu);
}

__device__ __forceinline__ float gmask(float u) { return expf(-12.5f * u * u); }
__device__ __forceinline__ constexpr int qidx(int k, int l) { return k*(9-k)/2 + l; }

__global__ __launch_bounds__(NTHREADS)
void tfmptf_kernel(const float* __restrict__ in, float* __restrict__ out)
{
    extern __shared__ char smraw[];
    Smem& sm = *reinterpret_cast<Smem*>(smraw);
    const int tid = threadIdx.x;
    const int bid = blockIdx.x;          // bid = b*64 + d
    const int d = bid & 63;
    const int b = bid >> 6;
    const int warp = tid >> 5;
    const int lane = tid & 31;

    // --- twiddles + input load + hist zero ---
    for (int j = tid; j < 1024; j += NTHREADS) {
        float sv, cv;
        sincospif(-(float)j * (1.0f/2048.0f), &sv, &cv); // -2*pi*j/4096
        sm.tw[j] = make_float2(cv, sv);
    }
    const float* xin = in + ((long)b * TLEN) * 64 + d;
    #pragma unroll
    for (int k = 0; k < 8; ++k) {
        int t = tid + k*NTHREADS;
        sm.buf0[SW(t)] = make_float2(__ldg(&xin[(long)t * 64]), 0.0f);
    }
    for (int i = tid; i < 16*36; i += NTHREADS) ((int*)sm.hist)[i] = 0;
    __syncthreads();

    // --- forward FFT: X in buf0 (swizzled) ---
    fft4096_r8<false>(sm.buf0, sm.buf0, sm.buf1, sm.tw, tid);

    // --- one mask pass: buf0 <- X*(S0+i*S1), xsave <- X*S2, grab X_nyq ---
    #pragma unroll
    for (int k = 0; k < 8; ++k) {
        int j = tid + k*NTHREADS;
        float2 X = sm.buf0[SW(j)];
        if (j == 2048) sm.xnyq = X.x;
        float f = (float)((j < 2048) ? j : (j - 4096)) * (1.0f/4096.0f);
        float S0 = 0.5f * (gmask(f + 0.5f) + gmask(f - 0.5f));   // k=0
        float S1 = 0.5f * (gmask(f - 0.3f) + gmask(f + 0.3f));   // k=1,4 merged
        float S2 = 0.5f * (gmask(f - 0.1f) + gmask(f + 0.1f));   // k=2,3 merged
        sm.buf0[SW(j)]  = make_float2(X.x*S0 - X.y*S1, X.x*S1 + X.y*S0);
        sm.xsave[SW(j)] = make_float2(X.x*S2, X.y*S2);
    }
    __syncthreads();

    // --- IFFT #1: modes 0 (Re) and 1 (Im) ---
    fft4096_r8<true>(sm.buf0, sm.buf0, sm.buf1, sm.tw, tid);
    #pragma unroll
    for (int k = 0; k < 8; ++k) {
        int t = tid + k*NTHREADS;
        float2 z = sm.buf0[SW(t)];
        sm.modes[0][t] = z.x * (1.0f/4096.0f);
        sm.modes[1][t] = z.y * (1.0f/4096.0f);
    }
    // --- IFFT #2 directly from xsave: mode 2 ---
    fft4096_r8<true>(sm.xsave, sm.buf0, sm.buf1, sm.tw, tid);
    #pragma unroll
    for (int k = 0; k < 8; ++k) {
        int t = tid + k*NTHREADS;
        sm.modes[2][t] = sm.buf0[SW(t)].x * (1.0f/4096.0f);
    }
    __syncthreads();

    // --- Nyquist rank-1 corrections: true mode_k(t) = merged_g(t) +- eps_g*(-1)^t
    const float xn = sm.xnyq * (1.0f/4096.0f);
    const float eg[3] = {
        0.5f * (1.0f        - expf(-12.5f)) * xn,
        0.5f * (expf(-0.5f) - expf(-8.0f))  * xn,
        0.5f * (expf(-2.0f) - expf(-4.5f))  * xn
    };

    // --- sliding-window permutation transitions: 5 modes, 4093 transitions ---
    {
        const int w0 = tid * 8;    // even, 32B-aligned
        #pragma unroll
        for (int g = 0; g < 3; ++g) {
            float4 A  = *(const float4*)(&sm.modes[g][w0]);
            float4 B4 = *(const float4*)(&sm.modes[g][w0+4]);
            float4 C4 = *(const float4*)(&sm.modes[g][w0+8]);   // padded row: safe
            float mv[12] = {A.x,A.y,A.z,A.w, B4.x,B4.y,B4.z,B4.w, C4.x,C4.y,C4.z,C4.w};
            const int nsign = (g == 0) ? 1 : 2;
            #pragma unroll
            for (int sv = 0; sv < 2; ++sv) {
                if (sv >= nsign) break;
                const float eps = (sv == 0) ? eg[g] : -eg[g];
                float vv[11];
                #pragma unroll
                for (int i = 0; i < 11; ++i)
                    vv[i] = mv[i] + ((i & 1) ? -eps : eps);
                int id[9];
                #pragma unroll
                for (int i = 0; i < 9; ++i)
                    id[i] = permid(vv[i], vv[i+1], vv[i+2]);
                #pragma unroll
                for (int i = 0; i < 8; ++i) {
                    bool valid = (w0 + i) < 4093;
                    int code = valid ? (id[i]*6 + id[i+1]) : 36;
                    unsigned grp = __match_any_sync(0xffffffffu, code);
                    if (valid && (int)(__ffs(grp) - 1) == lane)
                        atomicAdd(&sm.hist[warp][code], __popc(grp));
                }
            }
        }
    }

    // --- correlation moments over e_k = mode_k^2 (5 sums + 15 products) ---
    float S[5]; float Q[15];
    #pragma unroll
    for (int i = 0; i < 5; ++i) S[i] = 0.f;
    #pragma unroll
    for (int i = 0; i < 15; ++i) Q[i] = 0.f;
    #pragma unroll
    for (int k = 0; k < 8; ++k) {
        int t = tid + k*NTHREADS;
        float pe = (t & 1) ? -1.f : 1.f;
        float m0 = sm.modes[0][t], m1 = sm.modes[1][t], m2 = sm.modes[2][t];
        float v[5];
        v[0] = m0 + pe*eg[0];
        v[1] = m1 + pe*eg[1];
        v[2] = m2 + pe*eg[2];
        v[3] = m2 - pe*eg[2];
        v[4] = m1 - pe*eg[1];
        float e[5];
        #pragma unroll
        for (int kk = 0; kk < 5; ++kk) e[kk] = v[kk]*v[kk];
        #pragma unroll
        for (int kk = 0; kk < 5; ++kk) {
            S[kk] += e[kk];
            #pragma unroll
            for (int l = kk; l < 5; ++l)
                Q[qidx(kk,l)] = fmaf(e[kk], e[l], Q[qidx(kk,l)]);
        }
    }
    {
        float vvv[20];
        #pragma unroll
        for (int j = 0; j < 5; ++j)  vvv[j]   = S[j];
        #pragma unroll
        for (int j = 0; j < 15; ++j) vvv[5+j] = Q[j];
        #pragma unroll
        for (int j = 0; j < 20; ++j)
            #pragma unroll
            for (int off = 16; off; off >>= 1)
                vvv[j] += __shfl_down_sync(0xffffffffu, vvv[j], off);
        if (lane == 0)
            #pragma unroll
            for (int j = 0; j < 20; ++j) sm.red[warp][j] = vvv[j];
    }
    __syncthreads();

    if (tid < 36) {
        int ctot = 0;
        #pragma unroll
        for (int w = 0; w < 16; ++w) ctot += sm.hist[w][tid];
        sm.cnt[tid] = ctot;
    }
    if (tid < 20) {
        float tot = 0.f;
        #pragma unroll
        for (int w = 0; w < 16; ++w) tot += sm.red[w][tid];
        sm.totals[tid] = tot;
    }
    __syncthreads();

    float* outbd = out + (long)bid * 46;
    if (tid < 36) {
        int p = tid / 6;
        int rs = 0;
        #pragma unroll
        for (int q = 0; q < 6; ++q) rs += sm.cnt[p*6 + q];
        float denom = rs ? (float)rs : 1.0f;
        outbd[tid] = (float)sm.cnt[tid] / denom;
    }
    if (tid == 0) {
        const float invT = 1.0f / 4096.0f;
        float cov[15];
        #pragma unroll
        for (int k = 0; k < 5; ++k)
            #pragma unroll
            for (int l = k; l < 5; ++l)
                cov[qidx(k,l)] = sm.totals[5 + qidx(k,l)]
                               - sm.totals[k]*sm.totals[l]*invT;
        float dstd[5];
        #pragma unroll
        for (int k = 0; k < 5; ++k) dstd[k] = sqrtf(fmaxf(cov[qidx(k,k)], 0.f));
        int oi = 36;
        #pragma unroll
        for (int k = 0; k < 5; ++k) {
            #pragma unroll
            for (int l = k+1; l < 5; ++l) {
                float den = dstd[k] * dstd[l];
                float r = (den > 0.f) ? cov[qidx(k,l)] / den : 0.f;
                r = fminf(1.f, fmaxf(-1.f, r));
                outbd[oi++] = r;
            }
        }
    }
}

extern "C" void kernel_launch(void* const* d_in, const int* in_sizes, int n_in,
                              void* d_out, int out_size)
{
    (void)in_sizes; (void)n_in; (void)out_size;
    const float* in = (const float*)d_in[0];
    float* out = (float*)d_out;
    cudaFuncSetAttribute(tfmptf_kernel, cudaFuncAttributeMaxDynamicSharedMemorySize,
                         (int)sizeof(Smem));
    tfmptf_kernel<<<1024, NTHREADS, sizeof(Smem)>>>(in, out);
}

// round 4
// speedup vs baseline: 1.2081x; 1.2081x over previous
#include <cuda_runtime.h>

#define NTHREADS 512
#define TLEN 4096

#define SW(e) ((e) ^ ((((unsigned)(e))>>3)&15u))   // bank swizzle for FFT buffers

struct __align__(16) Smem {
    float2 buf0[TLEN];     // FFT ping; ends holding modes0/1 as .x/.y
    float2 buf1[TLEN];     // FFT pong
    float2 bufC[TLEN];     // Y2 = X*S2'; ends holding mode2 in .x
    float2 tw[1024];       // exp(-2*pi*i*j/4096), j<1024
    int    hist[16][36];
    float  red[16][20];
    float  totals[20];
    int    cnt[36];
    float  xnyq;
};

__device__ __forceinline__ float2 cadd(float2 a, float2 b){ return make_float2(a.x+b.x, a.y+b.y); }
__device__ __forceinline__ float2 csub(float2 a, float2 b){ return make_float2(a.x-b.x, a.y-b.y); }
__device__ __forceinline__ float2 cmul(float2 a, float2 b){
    return make_float2(fmaf(a.x,b.x,-a.y*b.y), fmaf(a.x,b.y, a.y*b.x));
}

// Stockham autosort radix-8 FFT, 4096 pts, 4 stages. Reads src0 on stage 0,
// ping-pongs bufB/bufA, result lands in bufA (natural order, swizzled layout).
template<bool INV>
__device__ void fft4096_r8(const float2* __restrict__ src0,
                           float2* __restrict__ bufA, float2* __restrict__ bufB,
                           const float2* __restrict__ tw, int tid)
{
    const float2* src = src0;
    float2* dst = bufB;
    #pragma unroll
    for (int stage = 0; stage < 4; ++stage) {
        const int slog = 3*stage;            // s = 8^stage
        const int p = tid >> slog;
        const int q = tid & ((1<<slog)-1);
        float2 x0 = src[SW(tid)];
        float2 x1 = src[SW(tid +  512)];
        float2 x2 = src[SW(tid + 1024)];
        float2 x3 = src[SW(tid + 1536)];
        float2 x4 = src[SW(tid + 2048)];
        float2 x5 = src[SW(tid + 2560)];
        float2 x6 = src[SW(tid + 3072)];
        float2 x7 = src[SW(tid + 3584)];
        const int ti = p << slog;            // p*s <= 511
        float2 w1 = tw[ti];
        float2 w2 = tw[2*ti];
        if (INV) { w1.y = -w1.y; w2.y = -w2.y; }
        float2 w3 = cmul(w1,w2);
        float2 w4 = cmul(w2,w2);
        float2 w5 = cmul(w2,w3);
        float2 w6 = cmul(w3,w3);
        float2 w7 = cmul(w3,w4);
        float2 t0=cadd(x0,x4), t1=cadd(x1,x5), t2=cadd(x2,x6), t3=cadd(x3,x7);
        float2 u0=csub(x0,x4), u1=csub(x1,x5), u2=csub(x2,x6), u3=csub(x3,x7);
        const float C8 = 0.70710678118654752f;
        const float2 om  = INV ? make_float2( C8,  C8) : make_float2( C8, -C8);
        const float2 om3 = INV ? make_float2(-C8,  C8) : make_float2(-C8, -C8);
        float2 v1 = cmul(u1, om);
        float2 v2 = INV ? make_float2(-u2.y, u2.x) : make_float2(u2.y, -u2.x);
        float2 v3 = cmul(u3, om3);
        float2 s02=cadd(t0,t2), d02=csub(t0,t2), s13=cadd(t1,t3), d13=csub(t1,t3);
        float2 jd = make_float2(-d13.y, d13.x);
        float2 X0 = cadd(s02, s13);
        float2 X4 = csub(s02, s13);
        float2 X2 = INV ? cadd(d02, jd) : csub(d02, jd);
        float2 X6 = INV ? csub(d02, jd) : cadd(d02, jd);
        float2 so=cadd(u0,v2), doo=csub(u0,v2), s13o=cadd(v1,v3), d13o=csub(v1,v3);
        float2 jdo = make_float2(-d13o.y, d13o.x);
        float2 X1 = cadd(so, s13o);
        float2 X5 = csub(so, s13o);
        float2 X3 = INV ? cadd(doo, jdo) : csub(doo, jdo);
        float2 X7 = INV ? csub(doo, jdo) : cadd(doo, jdo);
        const int st = 1 << slog;
        const int ob = q + (ti << 3);        // q + 8*s*p
        dst[SW(ob       )] = X0;
        dst[SW(ob +   st)] = cmul(w1, X1);
        dst[SW(ob + 2*st)] = cmul(w2, X2);
        dst[SW(ob + 3*st)] = cmul(w3, X3);
        dst[SW(ob + 4*st)] = cmul(w4, X4);
        dst[SW(ob + 5*st)] = cmul(w5, X5);
        dst[SW(ob + 6*st)] = cmul(w6, X6);
        dst[SW(ob + 7*st)] = cmul(w7, X7);
        __syncthreads();
        src = dst;
        dst = (dst == bufB) ? bufA : bufB;
    }
}

// Lehmer code of stable argsort of (a,b,c), matching reference id formula.
__device__ __forceinline__ int permid(float a, float b, float c)
{
    int i0 = (a <= b) ? 1 : 0;
    int i1 = (a <= c) ? 1 : 0;
    int i2 = (b <= c) ? 1 : 0;
    int idx = (i0 << 2) | (i1 << 1) | i2;
    const unsigned LUT = (5u<<0)|(3u<<4)|(0u<<8)|(2u<<12)|(4u<<16)|(0u<<20)|(1u<<24)|(0u<<28);
    return (int)((LUT >> (idx*4)) & 0xFu);
}

__device__ __forceinline__ float gmask(float u) { return expf(-12.5f * u * u); }
__device__ __forceinline__ constexpr int qidx(int k, int l) { return k*(9-k)/2 + l; }

__global__ __launch_bounds__(NTHREADS, 2)
void tfmptf_kernel(const float* __restrict__ in, float* __restrict__ out)
{
    extern __shared__ char smraw[];
    Smem& sm = *reinterpret_cast<Smem*>(smraw);
    const int tid = threadIdx.x;
    const int bid = blockIdx.x;          // bid = b*64 + d
    const int d = bid & 63;
    const int b = bid >> 6;
    const int warp = tid >> 5;
    const int lane = tid & 31;

    // --- twiddles + input load + hist zero ---
    for (int j = tid; j < 1024; j += NTHREADS) {
        float sv, cv;
        sincospif(-(float)j * (1.0f/2048.0f), &sv, &cv); // -2*pi*j/4096
        sm.tw[j] = make_float2(cv, sv);
    }
    const float* xin = in + ((long)b * TLEN) * 64 + d;
    #pragma unroll
    for (int k = 0; k < 8; ++k) {
        int t = tid + k*NTHREADS;
        sm.buf0[SW(t)] = make_float2(__ldg(&xin[(long)t * 64]), 0.0f);
    }
    for (int i = tid; i < 16*36; i += NTHREADS) ((int*)sm.hist)[i] = 0;
    __syncthreads();

    // --- forward FFT: X in buf0 ---
    fft4096_r8<false>(sm.buf0, sm.buf0, sm.buf1, sm.tw, tid);

    // --- mask pass (1/4096 folded in): buf0 <- X*(S0+iS1)', bufC <- X*S2' ---
    #pragma unroll
    for (int k = 0; k < 8; ++k) {
        int j = tid + k*NTHREADS;
        float2 X = sm.buf0[SW(j)];
        if (j == 2048) sm.xnyq = X.x;
        float f = (float)((j < 2048) ? j : (j - 4096)) * (1.0f/4096.0f);
        const float h = 0.5f * (1.0f/4096.0f);
        float S0 = h * (gmask(f + 0.5f) + gmask(f - 0.5f));   // k=0
        float S1 = h * (gmask(f - 0.3f) + gmask(f + 0.3f));   // k=1,4 merged
        float S2 = h * (gmask(f - 0.1f) + gmask(f + 0.1f));   // k=2,3 merged
        sm.buf0[SW(j)] = make_float2(X.x*S0 - X.y*S1, X.x*S1 + X.y*S0);
        sm.bufC[SW(j)] = make_float2(X.x*S2, X.y*S2);
    }
    __syncthreads();

    // --- IFFT #1: result in buf0 (mode0 = .x, mode1 = .y) ---
    fft4096_r8<true>(sm.buf0, sm.buf0, sm.buf1, sm.tw, tid);
    // --- IFFT #2: (bufC, buf1) ping-pong, result in bufC (mode2 = .x) ---
    fft4096_r8<true>(sm.bufC, sm.bufC, sm.buf1, sm.tw, tid);

    // --- Nyquist rank-1 corrections: true mode_k(t) = merged_g(t) +- eps_g*(-1)^t
    const float xn = sm.xnyq * (1.0f/4096.0f);
    const float eg[3] = {
        0.5f * (1.0f        - expf(-12.5f)) * xn,
        0.5f * (expf(-0.5f) - expf(-8.0f))  * xn,
        0.5f * (expf(-2.0f) - expf(-4.5f))  * xn
    };

    // --- sliding-window permutation transitions: 5 modes, 4093 transitions ---
    {
        const int w0 = tid * 8;
        float2 z01[11];
        #pragma unroll
        for (int i = 0; i < 11; ++i) {
            int e = w0 + i; e = (e < TLEN) ? e : (TLEN - 1);
            z01[i] = sm.buf0[SW(e)];
        }
        #pragma unroll
        for (int g = 0; g < 3; ++g) {
            float mv[11];
            if (g == 2) {
                #pragma unroll
                for (int i = 0; i < 11; ++i) {
                    int e = w0 + i; e = (e < TLEN) ? e : (TLEN - 1);
                    mv[i] = sm.bufC[SW(e)].x;
                }
            } else {
                #pragma unroll
                for (int i = 0; i < 11; ++i) mv[i] = (g == 0) ? z01[i].x : z01[i].y;
            }
            const int nsign = (g == 0) ? 1 : 2;
            #pragma unroll
            for (int sv = 0; sv < 2; ++sv) {
                if (sv >= nsign) break;
                const float eps = (sv == 0) ? eg[g] : -eg[g];
                float vv[11];
                #pragma unroll
                for (int i = 0; i < 11; ++i)
                    vv[i] = mv[i] + (((w0 + i) & 1) ? -eps : eps);
                int id[9];
                #pragma unroll
                for (int i = 0; i < 9; ++i)
                    id[i] = permid(vv[i], vv[i+1], vv[i+2]);
                #pragma unroll
                for (int i = 0; i < 8; ++i) {
                    bool valid = (w0 + i) < 4093;
                    int code = valid ? (id[i]*6 + id[i+1]) : 36;
                    unsigned grp = __match_any_sync(0xffffffffu, code);
                    if (valid && (int)(__ffs(grp) - 1) == lane)
                        atomicAdd(&sm.hist[warp][code], __popc(grp));
                }
            }
        }
    }

    // --- correlation moments over e_k = mode_k^2 (5 sums + 15 products) ---
    float S[5]; float Q[15];
    #pragma unroll
    for (int i = 0; i < 5; ++i) S[i] = 0.f;
    #pragma unroll
    for (int i = 0; i < 15; ++i) Q[i] = 0.f;
    #pragma unroll
    for (int k = 0; k < 8; ++k) {
        int t = tid + k*NTHREADS;
        float pe = (t & 1) ? -1.f : 1.f;
        float2 z = sm.buf0[SW(t)];
        float m2 = sm.bufC[SW(t)].x;
        float v[5];
        v[0] = z.x + pe*eg[0];
        v[1] = z.y + pe*eg[1];
        v[2] = m2  + pe*eg[2];
        v[3] = m2  - pe*eg[2];
        v[4] = z.y - pe*eg[1];
        float e[5];
        #pragma unroll
        for (int kk = 0; kk < 5; ++kk) e[kk] = v[kk]*v[kk];
        #pragma unroll
        for (int kk = 0; kk < 5; ++kk) {
            S[kk] += e[kk];
            #pragma unroll
            for (int l = kk; l < 5; ++l)
                Q[qidx(kk,l)] = fmaf(e[kk], e[l], Q[qidx(kk,l)]);
        }
    }
    {
        float vvv[20];
        #pragma unroll
        for (int j = 0; j < 5; ++j)  vvv[j]   = S[j];
        #pragma unroll
        for (int j = 0; j < 15; ++j) vvv[5+j] = Q[j];
        #pragma unroll
        for (int j = 0; j < 20; ++j)
            #pragma unroll
            for (int off = 16; off; off >>= 1)
                vvv[j] += __shfl_down_sync(0xffffffffu, vvv[j], off);
        if (lane == 0)
            #pragma unroll
            for (int j = 0; j < 20; ++j) sm.red[warp][j] = vvv[j];
    }
    __syncthreads();

    if (tid < 36) {
        int ctot = 0;
        #pragma unroll
        for (int w = 0; w < 16; ++w) ctot += sm.hist[w][tid];
        sm.cnt[tid] = ctot;
    }
    if (tid < 20) {
        float tot = 0.f;
        #pragma unroll
        for (int w = 0; w < 16; ++w) tot += sm.red[w][tid];
        sm.totals[tid] = tot;
    }
    __syncthreads();

    float* outbd = out + (long)bid * 46;
    if (tid < 36) {
        int p = tid / 6;
        int rs = 0;
        #pragma unroll
        for (int q = 0; q < 6; ++q) rs += sm.cnt[p*6 + q];
        float denom = rs ? (float)rs : 1.0f;
        outbd[tid] = (float)sm.cnt[tid] / denom;
    }
    if (tid == 0) {
        const float invT = 1.0f / 4096.0f;
        float cov[15];
        #pragma unroll
        for (int k = 0; k < 5; ++k)
            #pragma unroll
            for (int l = k; l < 5; ++l)
                cov[qidx(k,l)] = sm.totals[5 + qidx(k,l)]
                               - sm.totals[k]*sm.totals[l]*invT;
        float dstd[5];
        #pragma unroll
        for (int k = 0; k < 5; ++k) dstd[k] = sqrtf(fmaxf(cov[qidx(k,k)], 0.f));
        int oi = 36;
        #pragma unroll
        for (int k = 0; k < 5; ++k) {
            #pragma unroll
            for (int l = k+1; l < 5; ++l) {
                float den = dstd[k] * dstd[l];
                float r = (den > 0.f) ? cov[qidx(k,l)] / den : 0.f;
                r = fminf(1.f, fmaxf(-1.f, r));
                outbd[oi++] = r;
            }
        }
    }
}

extern "C" void kernel_launch(void* const* d_in, const int* in_sizes, int n_in,
                              void* d_out, int out_size)
{
    (void)in_sizes; (void)n_in; (void)out_size;
    const float* in = (const float*)d_in[0];
    float* out = (float*)d_out;
    cudaFuncSetAttribute(tfmptf_kernel, cudaFuncAttributeMaxDynamicSharedMemorySize,
                         (int)sizeof(Smem));
    tfmptf_kernel<<<1024, NTHREADS, sizeof(Smem)>>>(in, out);
}

// round 5
// speedup vs baseline: 1.2163x; 1.0068x over previous
#include <cuda_runtime.h>

#define NTHREADS 512
#define TLEN 4096

#define SW(e) ((e) ^ ((((unsigned)(e))>>3)&15u))   // bank swizzle for FFT buffers

__device__ float4 g_masks[TLEN];   // (S0,S1,S2,0) with 0.5/4096 folded in
__device__ float2 g_tw[1024];      // exp(-2*pi*i*j/4096)

struct __align__(16) Smem {
    float2 buf0[TLEN];     // FFT ping; ends holding modes0/1 as .x/.y
    float2 buf1[TLEN];     // FFT pong
    float2 bufC[TLEN];     // Y2 = X*S2'; ends holding mode2 in .x
    float2 tw[1024];
    int    hist[16][36];
    float  red[16][20];
    float  totals[20];
    int    cnt[36];
    float  xnyq;
};

__device__ __forceinline__ float2 cadd(float2 a, float2 b){ return make_float2(a.x+b.x, a.y+b.y); }
__device__ __forceinline__ float2 csub(float2 a, float2 b){ return make_float2(a.x-b.x, a.y-b.y); }
__device__ __forceinline__ float2 cmul(float2 a, float2 b){
    return make_float2(fmaf(a.x,b.x,-a.y*b.y), fmaf(a.x,b.y, a.y*b.x));
}

__global__ void init_tables()
{
    int j = blockIdx.x * blockDim.x + threadIdx.x;   // 0..4095
    if (j < 1024) {
        float sv, cv;
        sincospif(-(float)j * (1.0f/2048.0f), &sv, &cv); // -2*pi*j/4096
        g_tw[j] = make_float2(cv, sv);
    }
    float f = (float)((j < 2048) ? j : (j - 4096)) * (1.0f/4096.0f);
    const float h = 0.5f * (1.0f/4096.0f);
    float u;
    u = f + 0.5f; float a0 = expf(-12.5f*u*u);
    u = f - 0.5f; float a1 = expf(-12.5f*u*u);
    u = f - 0.3f; float b0 = expf(-12.5f*u*u);
    u = f + 0.3f; float b1 = expf(-12.5f*u*u);
    u = f - 0.1f; float c0 = expf(-12.5f*u*u);
    u = f + 0.1f; float c1 = expf(-12.5f*u*u);
    g_masks[j] = make_float4(h*(a0+a1), h*(b0+b1), h*(c0+c1), 0.f);
}

// Stockham autosort radix-8 FFT, 4096 pts, 4 stages. Reads src0 on stage 0,
// ping-pongs bufB/bufA, result lands in bufA (natural order, swizzled layout).
template<bool INV>
__device__ void fft4096_r8(const float2* __restrict__ src0,
                           float2* __restrict__ bufA, float2* __restrict__ bufB,
                           const float2* __restrict__ tw, int tid)
{
    const float2* src = src0;
    float2* dst = bufB;
    #pragma unroll
    for (int stage = 0; stage < 4; ++stage) {
        const int slog = 3*stage;            // s = 8^stage
        const int p = tid >> slog;
        const int q = tid & ((1<<slog)-1);
        float2 x0 = src[SW(tid)];
        float2 x1 = src[SW(tid +  512)];
        float2 x2 = src[SW(tid + 1024)];
        float2 x3 = src[SW(tid + 1536)];
        float2 x4 = src[SW(tid + 2048)];
        float2 x5 = src[SW(tid + 2560)];
        float2 x6 = src[SW(tid + 3072)];
        float2 x7 = src[SW(tid + 3584)];
        const int ti = p << slog;            // p*s <= 511
        float2 w1 = tw[ti];
        float2 w2 = tw[2*ti];
        if (INV) { w1.y = -w1.y; w2.y = -w2.y; }
        float2 w3 = cmul(w1,w2);
        float2 w4 = cmul(w2,w2);
        float2 w5 = cmul(w2,w3);
        float2 w6 = cmul(w3,w3);
        float2 w7 = cmul(w3,w4);
        float2 t0=cadd(x0,x4), t1=cadd(x1,x5), t2=cadd(x2,x6), t3=cadd(x3,x7);
        float2 u0=csub(x0,x4), u1=csub(x1,x5), u2=csub(x2,x6), u3=csub(x3,x7);
        const float C8 = 0.70710678118654752f;
        const float2 om  = INV ? make_float2( C8,  C8) : make_float2( C8, -C8);
        const float2 om3 = INV ? make_float2(-C8,  C8) : make_float2(-C8, -C8);
        float2 v1 = cmul(u1, om);
        float2 v2 = INV ? make_float2(-u2.y, u2.x) : make_float2(u2.y, -u2.x);
        float2 v3 = cmul(u3, om3);
        float2 s02=cadd(t0,t2), d02=csub(t0,t2), s13=cadd(t1,t3), d13=csub(t1,t3);
        float2 jd = make_float2(-d13.y, d13.x);
        float2 X0 = cadd(s02, s13);
        float2 X4 = csub(s02, s13);
        float2 X2 = INV ? cadd(d02, jd) : csub(d02, jd);
        float2 X6 = INV ? csub(d02, jd) : cadd(d02, jd);
        float2 so=cadd(u0,v2), doo=csub(u0,v2), s13o=cadd(v1,v3), d13o=csub(v1,v3);
        float2 jdo = make_float2(-d13o.y, d13o.x);
        float2 X1 = cadd(so, s13o);
        float2 X5 = csub(so, s13o);
        float2 X3 = INV ? cadd(doo, jdo) : csub(doo, jdo);
        float2 X7 = INV ? csub(doo, jdo) : cadd(doo, jdo);
        const int st = 1 << slog;
        const int ob = q + (ti << 3);        // q + 8*s*p
        dst[SW(ob       )] = X0;
        dst[SW(ob +   st)] = cmul(w1, X1);
        dst[SW(ob + 2*st)] = cmul(w2, X2);
        dst[SW(ob + 3*st)] = cmul(w3, X3);
        dst[SW(ob + 4*st)] = cmul(w4, X4);
        dst[SW(ob + 5*st)] = cmul(w5, X5);
        dst[SW(ob + 6*st)] = cmul(w6, X6);
        dst[SW(ob + 7*st)] = cmul(w7, X7);
        __syncthreads();
        src = dst;
        dst = (dst == bufB) ? bufA : bufB;
    }
}

// Lehmer code of stable argsort of (a,b,c), matching reference id formula.
__device__ __forceinline__ int permid(float a, float b, float c)
{
    int i0 = (a <= b) ? 1 : 0;
    int i1 = (a <= c) ? 1 : 0;
    int i2 = (b <= c) ? 1 : 0;
    int idx = (i0 << 2) | (i1 << 1) | i2;
    const unsigned LUT = (5u<<0)|(3u<<4)|(0u<<8)|(2u<<12)|(4u<<16)|(0u<<20)|(1u<<24)|(0u<<28);
    return (int)((LUT >> (idx*4)) & 0xFu);
}

__device__ __forceinline__ constexpr int qidx(int k, int l) { return k*(9-k)/2 + l; }

__global__ __launch_bounds__(NTHREADS, 2)
void tfmptf_kernel(const float* __restrict__ in, float* __restrict__ out)
{
    extern __shared__ char smraw[];
    Smem& sm = *reinterpret_cast<Smem*>(smraw);
    const int tid = threadIdx.x;
    const int bid = blockIdx.x;          // bid = b*64 + d
    const int d = bid & 63;
    const int b = bid >> 6;
    const int warp = tid >> 5;
    const int lane = tid & 31;

    // --- twiddles (gmem -> smem) + input load + hist zero ---
    for (int j = tid; j < 1024; j += NTHREADS)
        sm.tw[j] = g_tw[j];
    const float* xin = in + ((long)b * TLEN) * 64 + d;
    #pragma unroll
    for (int k = 0; k < 8; ++k) {
        int t = tid + k*NTHREADS;
        sm.buf0[SW(t)] = make_float2(__ldg(&xin[(long)t * 64]), 0.0f);
    }
    for (int i = tid; i < 16*36; i += NTHREADS) ((int*)sm.hist)[i] = 0;
    __syncthreads();

    // --- forward FFT: X in buf0 ---
    fft4096_r8<false>(sm.buf0, sm.buf0, sm.buf1, sm.tw, tid);

    // --- mask pass (tables from gmem): buf0 <- X*(S0+iS1)', bufC <- X*S2' ---
    #pragma unroll
    for (int k = 0; k < 8; ++k) {
        int j = tid + k*NTHREADS;
        float2 X = sm.buf0[SW(j)];
        if (j == 2048) sm.xnyq = X.x;
        float4 S = __ldg(&g_masks[j]);
        sm.buf0[SW(j)] = make_float2(X.x*S.x - X.y*S.y, X.x*S.y + X.y*S.x);
        sm.bufC[SW(j)] = make_float2(X.x*S.z, X.y*S.z);
    }
    __syncthreads();

    // --- IFFT #1: result in buf0 (mode0 = .x, mode1 = .y) ---
    fft4096_r8<true>(sm.buf0, sm.buf0, sm.buf1, sm.tw, tid);
    // --- IFFT #2: (bufC, buf1) ping-pong, result in bufC (mode2 = .x) ---
    fft4096_r8<true>(sm.bufC, sm.bufC, sm.buf1, sm.tw, tid);

    // --- Nyquist rank-1 corrections: true mode_k(t) = merged_g(t) +- eps_g*(-1)^t
    // coefficients: 0.5*(1-e^-12.5), 0.5*(e^-0.5-e^-8), 0.5*(e^-2-e^-4.5)
    const float xn = sm.xnyq * (1.0f/4096.0f);
    const float eg[3] = {
        0.49999813667341397f * xn,
        0.30309759854236545f * xn,
        0.06211314334918520f * xn
    };

    // --- sliding-window permutation transitions: 5 modes, 4093 transitions ---
    {
        const int w0 = tid * 8;
        float2 z01[11];
        #pragma unroll
        for (int i = 0; i < 11; ++i) {
            int e = w0 + i; e = (e < TLEN) ? e : (TLEN - 1);
            z01[i] = sm.buf0[SW(e)];
        }
        #pragma unroll
        for (int g = 0; g < 3; ++g) {
            float mv[11];
            if (g == 2) {
                #pragma unroll
                for (int i = 0; i < 11; ++i) {
                    int e = w0 + i; e = (e < TLEN) ? e : (TLEN - 1);
                    mv[i] = sm.bufC[SW(e)].x;
                }
            } else {
                #pragma unroll
                for (int i = 0; i < 11; ++i) mv[i] = (g == 0) ? z01[i].x : z01[i].y;
            }
            const int nsign = (g == 0) ? 1 : 2;
            #pragma unroll
            for (int sv = 0; sv < 2; ++sv) {
                if (sv >= nsign) break;
                const float eps = (sv == 0) ? eg[g] : -eg[g];
                float vv[11];
                #pragma unroll
                for (int i = 0; i < 11; ++i)
                    vv[i] = mv[i] + (((w0 + i) & 1) ? -eps : eps);
                int id[9];
                #pragma unroll
                for (int i = 0; i < 9; ++i)
                    id[i] = permid(vv[i], vv[i+1], vv[i+2]);
                #pragma unroll
                for (int i = 0; i < 8; ++i) {
                    bool valid = (w0 + i) < 4093;
                    int code = valid ? (id[i]*6 + id[i+1]) : 36;
                    unsigned grp = __match_any_sync(0xffffffffu, code);
                    if (valid && (int)(__ffs(grp) - 1) == lane)
                        atomicAdd(&sm.hist[warp][code], __popc(grp));
                }
            }
        }
    }

    // --- correlation moments over e_k = mode_k^2 (5 sums + 15 products) ---
    float S[5]; float Q[15];
    #pragma unroll
    for (int i = 0; i < 5; ++i) S[i] = 0.f;
    #pragma unroll
    for (int i = 0; i < 15; ++i) Q[i] = 0.f;
    #pragma unroll
    for (int k = 0; k < 8; ++k) {
        int t = tid + k*NTHREADS;
        float pe = (t & 1) ? -1.f : 1.f;
        float2 z = sm.buf0[SW(t)];
        float m2 = sm.bufC[SW(t)].x;
        float v[5];
        v[0] = z.x + pe*eg[0];
        v[1] = z.y + pe*eg[1];
        v[2] = m2  + pe*eg[2];
        v[3] = m2  - pe*eg[2];
        v[4] = z.y - pe*eg[1];
        float e[5];
        #pragma unroll
        for (int kk = 0; kk < 5; ++kk) e[kk] = v[kk]*v[kk];
        #pragma unroll
        for (int kk = 0; kk < 5; ++kk) {
            S[kk] += e[kk];
            #pragma unroll
            for (int l = kk; l < 5; ++l)
                Q[qidx(kk,l)] = fmaf(e[kk], e[l], Q[qidx(kk,l)]);
        }
    }
    {
        float vvv[20];
        #pragma unroll
        for (int j = 0; j < 5; ++j)  vvv[j]   = S[j];
        #pragma unroll
        for (int j = 0; j < 15; ++j) vvv[5+j] = Q[j];
        #pragma unroll
        for (int j = 0; j < 20; ++j)
            #pragma unroll
            for (int off = 16; off; off >>= 1)
                vvv[j] += __shfl_down_sync(0xffffffffu, vvv[j], off);
        if (lane == 0)
            #pragma unroll
            for (int j = 0; j < 20; ++j) sm.red[warp][j] = vvv[j];
    }
    __syncthreads();

    if (tid < 36) {
        int ctot = 0;
        #pragma unroll
        for (int w = 0; w < 16; ++w) ctot += sm.hist[w][tid];
        sm.cnt[tid] = ctot;
    }
    if (tid < 20) {
        float tot = 0.f;
        #pragma unroll
        for (int w = 0; w < 16; ++w) tot += sm.red[w][tid];
        sm.totals[tid] = tot;
    }
    __syncthreads();

    float* outbd = out + (long)bid * 46;
    if (tid < 36) {
        int p = tid / 6;
        int rs = 0;
        #pragma unroll
        for (int q = 0; q < 6; ++q) rs += sm.cnt[p*6 + q];
        float denom = rs ? (float)rs : 1.0f;
        outbd[tid] = (float)sm.cnt[tid] / denom;
    }
    if (tid == 0) {
        const float invT = 1.0f / 4096.0f;
        float cov[15];
        #pragma unroll
        for (int k = 0; k < 5; ++k)
            #pragma unroll
            for (int l = k; l < 5; ++l)
                cov[qidx(k,l)] = sm.totals[5 + qidx(k,l)]
                               - sm.totals[k]*sm.totals[l]*invT;
        float dstd[5];
        #pragma unroll
        for (int k = 0; k < 5; ++k) dstd[k] = sqrtf(fmaxf(cov[qidx(k,k)], 0.f));
        int oi = 36;
        #pragma unroll
        for (int k = 0; k < 5; ++k) {
            #pragma unroll
            for (int l = k+1; l < 5; ++l) {
                float den = dstd[k] * dstd[l];
                float r = (den > 0.f) ? cov[qidx(k,l)] / den : 0.f;
                r = fminf(1.f, fmaxf(-1.f, r));
                outbd[oi++] = r;
            }
        }
    }
}

extern "C" void kernel_launch(void* const* d_in, const int* in_sizes, int n_in,
                              void* d_out, int out_size)
{
    (void)in_sizes; (void)n_in; (void)out_size;
    const float* in = (const float*)d_in[0];
    float* out = (float*)d_out;
    init_tables<<<8, 512>>>();
    cudaFuncSetAttribute(tfmptf_kernel, cudaFuncAttributeMaxDynamicSharedMemorySize,
                         (int)sizeof(Smem));
    tfmptf_kernel<<<1024, NTHREADS, sizeof(Smem)>>>(in, out);
}